// round 7
// baseline (speedup 1.0000x reference)
#include <cuda_runtime.h>
#include <cstdint>
#include <math.h>
#include <float.h>

#define BD 2
#define TT 2048
#define DDIM 2048
#define NH 16
#define HD 128
#define BH (BD*NH)         // 32
#define MROWS (BD*TT)      // 4096
#define E3 (3*DDIM)        // 6144
#define SCALE 0.08838834764831843f

// K-chunk = 16. A: 128x16 tf32 = 8192B. B: 16 blocks x 2 ks x 264B = 8448B.
#define ABYTES 8192
#define BUFSZ  16640
#define SMEM_MAIN (2*BUFSZ)        // 33280
#define SMEM_QKV  (128*132*4)      // 67584 (epilogue staging union)

// ------------------ scratch (static device, allocation-free) ------------------
__device__ float g_q[(size_t)BH*TT*HD];
__device__ float g_k[(size_t)BH*TT*HD];
__device__ float g_vt[(size_t)BH*HD*TT];      // V transposed: [bh][d][t]
__device__ float g_s[(size_t)BH*TT*TT];       // raw scaled scores, 512MB
__device__ float g_attn[(size_t)MROWS*DDIM];

// ------------------ helpers ------------------
static __device__ __forceinline__ uint32_t f2tf32(float x){
    uint32_t y; asm("cvt.rn.tf32.f32 %0, %1;" : "=r"(y) : "f"(x)); return y;
}

static __device__ __forceinline__ void mma8(float* c, const uint4& a, const uint2& b){
    asm volatile(
        "mma.sync.aligned.m16n8k8.row.col.f32.tf32.tf32.f32 "
        "{%0,%1,%2,%3}, {%4,%5,%6,%7}, {%8,%9}, {%0,%1,%2,%3};"
        : "+f"(c[0]), "+f"(c[1]), "+f"(c[2]), "+f"(c[3])
        : "r"(a.x), "r"(a.y), "r"(a.z), "r"(a.w), "r"(b.x), "r"(b.y));
}

// store one element (row r of tile, k in 0..15) into fragment-order smem
static __device__ __forceinline__ void stage_one(char* buf, float va, float vb, int r, int k){
    const int ks = k >> 3, t = k & 3, thi = (k >> 2) & 1;
    const int g = r & 7;
    const int s = 4*g + ((t + (g >> 1)) & 3);
    const int mi2 = r >> 4, hi = (r >> 3) & 1;
    *(uint32_t*)(buf + (((mi2*2 + ks) << 9) + s*16 + (hi + 2*thi)*4)) = f2tf32(va);
    const int ntB = r >> 3;
    *(uint32_t*)(buf + (ABYTES + (ntB*2 + ks)*264 + s*8 + thi*4)) = f2tf32(vb);
}

static __device__ __forceinline__ void stage4(char* buf, const float4& va, const float4& vb,
                                              int r, int cc){
    const float av[4] = {va.x, va.y, va.z, va.w};
    const float bv[4] = {vb.x, vb.y, vb.z, vb.w};
    #pragma unroll
    for (int dt = 0; dt < 4; dt++) stage_one(buf, av[dt], bv[dt], r, cc*4 + dt);
}

// PV variant: A gets softmax transform + causal mask; B is plain
static __device__ __forceinline__ void stage4_pv(char* buf, const float4& va, const float4& vb,
                                                 int r, int cc, int jbase, float m, float inv, int L){
    const float av[4] = {va.x, va.y, va.z, va.w};
    const float bv[4] = {vb.x, vb.y, vb.z, vb.w};
    #pragma unroll
    for (int dt = 0; dt < 4; dt++){
        const int k = cc*4 + dt;
        const float a = (jbase + k < L) ? __expf(av[dt] - m) * inv : 0.f;
        stage_one(buf, a, bv[dt], r, k);
    }
}

static __device__ __forceinline__ void compute_chunk(const char* buf, float (&acc)[4][4][4],
                                                     int wm, int wn, int l)
{
    const int g = l >> 2;
    const int sig = 4*g + (((l & 3) + (g >> 1)) & 3);
    const int sa16 = sig * 16;
    const int sb8  = sig * 8;
    #pragma unroll
    for (int ks = 0; ks < 2; ks++){
        uint4 a[4]; uint2 b[4];
        #pragma unroll
        for (int mi = 0; mi < 4; mi++)
            a[mi] = *(const uint4*)(buf + ((((wm*4 + mi)*2 + ks) << 9) + sa16));
        #pragma unroll
        for (int ni = 0; ni < 4; ni++)
            b[ni] = *(const uint2*)(buf + (ABYTES + ((wn*4 + ni)*2 + ks)*264 + sb8));
        #pragma unroll
        for (int mi = 0; mi < 4; mi++)
            #pragma unroll
            for (int ni = 0; ni < 4; ni++)
                mma8(acc[mi][ni], a[mi], b[ni]);
    }
}

// C[128,128] += A[128,K] * B[128,K]^T, K = nIter*16.
static __device__ __forceinline__ void gemm_loop(char* sm, float (&acc)[4][4][4],
    const float* __restrict__ A, size_t lda,
    const float* __restrict__ B, size_t ldb, int nIter)
{
    const int tid = threadIdx.x;
    const int r = tid & 127, ccb = (tid >> 7) * 2;
    const int w = tid >> 5, wm = w >> 2, wn = w & 3, l = tid & 31;
    const float* Ar = A + (size_t)r * lda;
    const float* Br = B + (size_t)r * ldb;

    float4 pa[2], pb[2];
    #pragma unroll
    for (int i = 0; i < 2; i++){
        pa[i] = *(const float4*)(Ar + (ccb + i)*4);
        pb[i] = *(const float4*)(Br + (ccb + i)*4);
    }
    #pragma unroll
    for (int i = 0; i < 2; i++) stage4(sm, pa[i], pb[i], r, ccb + i);
    if (nIter > 1){
        #pragma unroll
        for (int i = 0; i < 2; i++){
            pa[i] = *(const float4*)(Ar + 16 + (ccb + i)*4);
            pb[i] = *(const float4*)(Br + 16 + (ccb + i)*4);
        }
    }
    __syncthreads();

    for (int kt = 0; kt < nIter; kt++){
        char* cur = sm + (kt & 1) * BUFSZ;
        if (kt + 1 < nIter){
            char* nxt = sm + ((kt + 1) & 1) * BUFSZ;
            #pragma unroll
            for (int i = 0; i < 2; i++) stage4(nxt, pa[i], pb[i], r, ccb + i);
        }
        if (kt + 2 < nIter){
            const int ko = (kt + 2) * 16;
            #pragma unroll
            for (int i = 0; i < 2; i++){
                pa[i] = *(const float4*)(Ar + ko + (ccb + i)*4);
                pb[i] = *(const float4*)(Br + ko + (ccb + i)*4);
            }
        }
        compute_chunk(cur, acc, wm, wn, l);
        __syncthreads();
    }
}

// PV version: A staged through softmax transform (per-row m/inv, causal mask)
static __device__ __forceinline__ void gemm_loop_pv(char* sm, float (&acc)[4][4][4],
    const float* __restrict__ A, size_t lda,
    const float* __restrict__ B, size_t ldb, int nIter,
    const float* __restrict__ sM, const float* __restrict__ sInv, int m0)
{
    const int tid = threadIdx.x;
    const int r = tid & 127, ccb = (tid >> 7) * 2;
    const int w = tid >> 5, wm = w >> 2, wn = w & 3, l = tid & 31;
    const float* Ar = A + (size_t)r * lda;
    const float* Br = B + (size_t)r * ldb;
    const float mrow = sM[r], inv = sInv[r];
    const int L = m0 + r + 1;

    float4 pa[2], pb[2];
    #pragma unroll
    for (int i = 0; i < 2; i++){
        pa[i] = *(const float4*)(Ar + (ccb + i)*4);
        pb[i] = *(const float4*)(Br + (ccb + i)*4);
    }
    #pragma unroll
    for (int i = 0; i < 2; i++) stage4_pv(sm, pa[i], pb[i], r, ccb + i, 0, mrow, inv, L);
    if (nIter > 1){
        #pragma unroll
        for (int i = 0; i < 2; i++){
            pa[i] = *(const float4*)(Ar + 16 + (ccb + i)*4);
            pb[i] = *(const float4*)(Br + 16 + (ccb + i)*4);
        }
    }
    __syncthreads();

    for (int kt = 0; kt < nIter; kt++){
        char* cur = sm + (kt & 1) * BUFSZ;
        if (kt + 1 < nIter){
            char* nxt = sm + ((kt + 1) & 1) * BUFSZ;
            #pragma unroll
            for (int i = 0; i < 2; i++)
                stage4_pv(nxt, pa[i], pb[i], r, ccb + i, (kt + 1)*16, mrow, inv, L);
        }
        if (kt + 2 < nIter){
            const int ko = (kt + 2) * 16;
            #pragma unroll
            for (int i = 0; i < 2; i++){
                pa[i] = *(const float4*)(Ar + ko + (ccb + i)*4);
                pb[i] = *(const float4*)(Br + ko + (ccb + i)*4);
            }
        }
        compute_chunk(cur, acc, wm, wn, l);
        __syncthreads();
    }
}

#define GEMM_PROLOGUE() \
    extern __shared__ char sm[]; \
    const int tid = threadIdx.x; \
    const int w = tid >> 5, wm = w >> 2, wn = w & 3, l = tid & 31; \
    const int fg = l >> 2, ft = l & 3; \
    float acc[4][4][4]; \
    _Pragma("unroll") for (int mi = 0; mi < 4; mi++) \
    _Pragma("unroll") for (int ni = 0; ni < 4; ni++) \
    _Pragma("unroll") for (int j = 0; j < 4; j++) acc[mi][ni][j] = 0.f;

// ======================= QKV GEMM + fused bias/RoPE + V transpose =======================
__global__ __launch_bounds__(256, 2) void k_qkv(const float* __restrict__ X,
                                                const float* __restrict__ W,
                                                const float* __restrict__ bias,
                                                const float* __restrict__ cs,
                                                const float* __restrict__ sn)
{
    GEMM_PROLOGUE();
    const int n0 = blockIdx.x * 128, m0 = blockIdx.y * 128;
    gemm_loop(sm, acc, X + (size_t)m0*DDIM, DDIM, W + (size_t)n0*DDIM, DDIM, DDIM/16);

    float* smC = (float*)sm;
    #pragma unroll
    for (int ni = 0; ni < 4; ni++){
        const int c = 32*wn + 8*ni + 2*ft;
        const float b0 = bias[n0 + c], b1 = bias[n0 + c + 1];
        #pragma unroll
        for (int mi = 0; mi < 4; mi++){
            const int rr = 64*wm + 16*mi + fg;
            smC[rr*132 + c]     = acc[mi][ni][0] + b0;
            smC[rr*132 + c + 1] = acc[mi][ni][1] + b1;
            smC[(rr+8)*132 + c]     = acc[mi][ni][2] + b0;
            smC[(rr+8)*132 + c + 1] = acc[mi][ni][3] + b1;
        }
    }
    __syncthreads();

    const int s = n0 >> 11, h = (n0 & 2047) >> 7;
    const int bb = m0 >> 11, t0 = m0 & 2047;
    if (s < 2){
        const int r = tid & 127, half = tid >> 7;
        const int t = t0 + r;
        float* dst = (s ? g_k : g_q) + ((size_t)(bb*NH + h)*TT + t)*HD;
        const float* csr = cs + (size_t)t*HD;
        const float* snr = sn + (size_t)t*HD;
        #pragma unroll
        for (int jj = 0; jj < 8; jj++){
            const int c = half*32 + jj*4;
            float4 x1 = *(const float4*)(smC + r*132 + c);
            float4 x2 = *(const float4*)(smC + r*132 + c + 64);
            float4 c0 = *(const float4*)(csr + c);
            float4 s0 = *(const float4*)(snr + c);
            float4 c1 = *(const float4*)(csr + c + 64);
            float4 s1 = *(const float4*)(snr + c + 64);
            float4 o1 = make_float4(x1.x*c0.x - x2.x*s0.x, x1.y*c0.y - x2.y*s0.y,
                                    x1.z*c0.z - x2.z*s0.z, x1.w*c0.w - x2.w*s0.w);
            float4 o2 = make_float4(x2.x*c1.x + x1.x*s1.x, x2.y*c1.y + x1.y*s1.y,
                                    x2.z*c1.z + x1.z*s1.z, x2.w*c1.w + x1.w*s1.w);
            *(float4*)(dst + c)      = o1;
            *(float4*)(dst + c + 64) = o2;
        }
    } else {
        float* dstb = g_vt + (size_t)(bb*NH + h)*HD*TT;
        #pragma unroll
        for (int i = 0; i < 16; i++){
            const int ii = tid + i*256;
            const int d = ii >> 5, tq = ii & 31;
            float4 v;
            v.x = smC[(tq*4 + 0)*132 + d];
            v.y = smC[(tq*4 + 1)*132 + d];
            v.z = smC[(tq*4 + 2)*132 + d];
            v.w = smC[(tq*4 + 3)*132 + d];
            *(float4*)(dstb + (size_t)d*TT + t0 + tq*4) = v;
        }
    }
}

// ======================= Scores: S = scale * Q K^T, lower tiles only (raw, no softmax) =======================
__global__ __launch_bounds__(256, 2) void k_scores()
{
    if (blockIdx.x > blockIdx.y) return;
    GEMM_PROLOGUE();
    const int bh = blockIdx.z;
    const int m0 = blockIdx.y * 128, n0 = blockIdx.x * 128;
    gemm_loop(sm, acc,
              g_q + (size_t)bh*TT*HD + (size_t)m0*HD, HD,
              g_k + (size_t)bh*TT*HD + (size_t)n0*HD, HD, HD/16);
    float* C = g_s + (size_t)bh*TT*TT;
    #pragma unroll
    for (int mi = 0; mi < 4; mi++){
        const int rl = m0 + 64*wm + 16*mi + fg;
        #pragma unroll
        for (int ni = 0; ni < 4; ni++){
            const int c = n0 + 32*wn + 8*ni + 2*ft;
            *(float2*)(C + (size_t)rl*TT + c)     = make_float2(acc[mi][ni][0]*SCALE, acc[mi][ni][1]*SCALE);
            *(float2*)(C + (size_t)(rl+8)*TT + c) = make_float2(acc[mi][ni][2]*SCALE, acc[mi][ni][3]*SCALE);
        }
    }
}

// ======================= PV with fused softmax: O = softmax(S) * V =======================
__global__ __launch_bounds__(256, 2) void k_pv()
{
    __shared__ float sM[128], sInv[128];
    GEMM_PROLOGUE();
    const int mt = blockIdx.x, bh = blockIdx.y;
    const int m0 = mt * 128;
    const float* Srow = g_s + (size_t)bh*TT*TT + (size_t)m0*TT;

    // phase 1: per-row online max/sum over causal length
    #pragma unroll 1
    for (int rr = 0; rr < 16; rr++){
        const int r = w*16 + rr;
        const int L = m0 + r + 1;
        const float* row = Srow + (size_t)r*TT;
        float mloc = -FLT_MAX, sloc = 0.f;
        for (int j0 = l*4; j0 < L; j0 += 128){
            float4 v4 = *(const float4*)(row + j0);
            const float vx[4] = {v4.x, v4.y, v4.z, v4.w};
            float m4 = -FLT_MAX;
            #pragma unroll
            for (int e = 0; e < 4; e++) if (j0 + e < L) m4 = fmaxf(m4, vx[e]);
            if (m4 > mloc){ sloc *= __expf(mloc - m4); mloc = m4; }
            #pragma unroll
            for (int e = 0; e < 4; e++) if (j0 + e < L) sloc += __expf(vx[e] - mloc);
        }
        #pragma unroll
        for (int o = 16; o; o >>= 1){
            const float mo = __shfl_xor_sync(0xffffffffu, mloc, o);
            const float so = __shfl_xor_sync(0xffffffffu, sloc, o);
            const float mn = fmaxf(mloc, mo);
            sloc = sloc*__expf(mloc - mn) + so*__expf(mo - mn);
            mloc = mn;
        }
        if (l == 0){ sM[r] = mloc; sInv[r] = 1.f / sloc; }
    }
    __syncthreads();

    gemm_loop_pv(sm, acc,
                 Srow, TT,
                 g_vt + (size_t)bh*HD*TT, TT, (mt + 1) * 8,
                 sM, sInv, m0);

    const int bb = bh >> 4, h = bh & 15;
    #pragma unroll
    for (int mi = 0; mi < 4; mi++){
        const int m = m0 + 64*wm + 16*mi + fg;
        float* d0 = g_attn + ((size_t)(bb*TT + m))*DDIM + h*HD;
        float* d1 = g_attn + ((size_t)(bb*TT + m + 8))*DDIM + h*HD;
        #pragma unroll
        for (int ni = 0; ni < 4; ni++){
            const int c = 32*wn + 8*ni + 2*ft;
            *(float2*)(d0 + c) = make_float2(acc[mi][ni][0], acc[mi][ni][1]);
            *(float2*)(d1 + c) = make_float2(acc[mi][ni][2], acc[mi][ni][3]);
        }
    }
}

// ======================= Output projection =======================
__global__ __launch_bounds__(256, 2) void k_out(const float* __restrict__ W,
                                                const float* __restrict__ bias,
                                                float* __restrict__ Cout)
{
    GEMM_PROLOGUE();
    const int n0 = blockIdx.x * 128, m0 = blockIdx.y * 128;
    gemm_loop(sm, acc, g_attn + (size_t)m0*DDIM, DDIM, W + (size_t)n0*DDIM, DDIM, DDIM/16);
    #pragma unroll
    for (int ni = 0; ni < 4; ni++){
        const int c = n0 + 32*wn + 8*ni + 2*ft;
        const float b0 = bias[c], b1 = bias[c + 1];
        #pragma unroll
        for (int mi = 0; mi < 4; mi++){
            const int m = m0 + 64*wm + 16*mi + fg;
            *(float2*)(Cout + (size_t)m*DDIM + c)     = make_float2(acc[mi][ni][0] + b0, acc[mi][ni][1] + b1);
            *(float2*)(Cout + (size_t)(m+8)*DDIM + c) = make_float2(acc[mi][ni][2] + b0, acc[mi][ni][3] + b1);
        }
    }
}

// ======================= launch =======================
extern "C" void kernel_launch(void* const* d_in, const int* in_sizes, int n_in,
                              void* d_out, int out_size)
{
    (void)in_sizes; (void)n_in; (void)out_size;
    const float* x      = (const float*)d_in[0];
    const float* rc     = (const float*)d_in[1];
    const float* rs     = (const float*)d_in[2];
    const float* qkv_w  = (const float*)d_in[3];
    const float* qkv_b  = (const float*)d_in[4];
    const float* out_w  = (const float*)d_in[5];
    const float* out_b  = (const float*)d_in[6];
    float* out = (float*)d_out;

    cudaFuncSetAttribute(k_qkv,    cudaFuncAttributeMaxDynamicSharedMemorySize, SMEM_QKV);
    cudaFuncSetAttribute(k_scores, cudaFuncAttributeMaxDynamicSharedMemorySize, SMEM_MAIN);
    cudaFuncSetAttribute(k_pv,     cudaFuncAttributeMaxDynamicSharedMemorySize, SMEM_MAIN);
    cudaFuncSetAttribute(k_out,    cudaFuncAttributeMaxDynamicSharedMemorySize, SMEM_MAIN);

    k_qkv<<<dim3(E3/128, MROWS/128), 256, SMEM_QKV>>>(x, qkv_w, qkv_b, rc, rs);
    k_scores<<<dim3(TT/128, TT/128, BH), 256, SMEM_MAIN>>>();
    k_pv<<<dim3(TT/128, BH), 256, SMEM_MAIN>>>();
    k_out<<<dim3(DDIM/128, MROWS/128), 256, SMEM_MAIN>>>(out_w, out_b, out);
}

// round 8
// speedup vs baseline: 1.6548x; 1.6548x over previous
#include <cuda_runtime.h>
#include <cstdint>
#include <math.h>
#include <float.h>

#define BD 2
#define TT 2048
#define DDIM 2048
#define NH 16
#define HD 128
#define BH (BD*NH)         // 32
#define MROWS (BD*TT)      // 4096
#define E3 (3*DDIM)        // 6144
#define SCALE 0.08838834764831843f

// K-chunk 16, row pitch 80B (16 floats + 16B pad -> conflict-free ldmatrix)
#define PITCH 80
#define ASZ (128*PITCH)            // 10240
#define STG (2*ASZ)                // 20480 per stage (A+B)
#define SMEM_ALL (4*STG)           // 81920 (4 stages; also covers 67584 qkv epilogue staging)

// ------------------ scratch (static device, allocation-free) ------------------
__device__ float g_x [(size_t)MROWS*DDIM];    // tf32-rounded X
__device__ float g_w [(size_t)E3*DDIM];       // tf32-rounded qkv_w
__device__ float g_wo[(size_t)DDIM*DDIM];     // tf32-rounded out_w
__device__ float g_q[(size_t)BH*TT*HD];       // tf32-rounded (RoPE'd)
__device__ float g_k[(size_t)BH*TT*HD];
__device__ float g_vt[(size_t)BH*HD*TT];      // V transposed [bh][d][t], tf32-rounded
__device__ float g_s[(size_t)BH*TT*TT];       // raw scaled scores (fp32)
__device__ float g_attn[(size_t)MROWS*DDIM];  // tf32-rounded

// ------------------ helpers ------------------
static __device__ __forceinline__ uint32_t smem_u32(const void* p){
    uint32_t a;
    asm("{ .reg .u64 t; cvta.to.shared.u64 t, %1; cvt.u32.u64 %0, t; }" : "=r"(a) : "l"(p));
    return a;
}
static __device__ __forceinline__ uint32_t f2tf32(float x){
    uint32_t y; asm("cvt.rn.tf32.f32 %0, %1;" : "=r"(y) : "f"(x)); return y;
}
static __device__ __forceinline__ float rnd(float x){ return __uint_as_float(f2tf32(x)); }

static __device__ __forceinline__ void cp16(uint32_t dst, const void* src){
    uint64_t g;
    asm("cvta.to.global.u64 %0, %1;" : "=l"(g) : "l"(src));
    asm volatile("cp.async.ca.shared.global [%0], [%1], 16;" :: "r"(dst), "l"(g) : "memory");
}
#define CP_COMMIT() asm volatile("cp.async.commit_group;" ::: "memory")
#define CP_WAIT2()  asm volatile("cp.async.wait_group 2;" ::: "memory")

#define LDMX4(r, addr) asm volatile( \
    "ldmatrix.sync.aligned.m8n8.x4.shared.b16 {%0,%1,%2,%3}, [%4];" \
    : "=r"((r)[0]),"=r"((r)[1]),"=r"((r)[2]),"=r"((r)[3]) : "r"(addr))
#define LDMX2(r, addr) asm volatile( \
    "ldmatrix.sync.aligned.m8n8.x2.shared.b16 {%0,%1}, [%2];" \
    : "=r"((r)[0]),"=r"((r)[1]) : "r"(addr))

static __device__ __forceinline__ void mma8(float* c, const uint32_t* a, const uint32_t* b){
    asm volatile(
        "mma.sync.aligned.m16n8k8.row.col.f32.tf32.tf32.f32 "
        "{%0,%1,%2,%3}, {%4,%5,%6,%7}, {%8,%9}, {%0,%1,%2,%3};"
        : "+f"(c[0]), "+f"(c[1]), "+f"(c[2]), "+f"(c[3])
        : "r"(a[0]), "r"(a[1]), "r"(a[2]), "r"(a[3]), "r"(b[0]), "r"(b[1]));
}

// compute one K=16 chunk from a stage (ldmatrix fragments, 32 MMA/warp)
static __device__ __forceinline__ void compute16(uint32_t stg, float (&acc)[4][4][4],
                                                 int aoff, int boff)
{
    #pragma unroll
    for (int ks = 0; ks < 2; ks++){
        uint32_t a[4][4], b[4][2];
        #pragma unroll
        for (int mi = 0; mi < 4; mi++)
            LDMX4(a[mi], stg + aoff + mi*(16*PITCH) + ks*32);
        #pragma unroll
        for (int ni = 0; ni < 4; ni++)
            LDMX2(b[ni], stg + ASZ + boff + ni*(8*PITCH) + ks*32);
        #pragma unroll
        for (int mi = 0; mi < 4; mi++)
            #pragma unroll
            for (int ni = 0; ni < 4; ni++)
                mma8(acc[mi][ni], a[mi], b[ni]);
    }
}

// issue cp.async loads for one chunk into a stage
static __device__ __forceinline__ void cp_issue(uint32_t stg,
    const float* __restrict__ A, size_t lda,
    const float* __restrict__ B, size_t ldb, int k0, int tid)
{
    #pragma unroll
    for (int j = 0; j < 2; j++){
        const int u = tid + 256*j;
        const int row = u >> 2, kc = u & 3;
        cp16(stg + row*PITCH + kc*16,       A + (size_t)row*lda + k0 + kc*4);
        cp16(stg + ASZ + row*PITCH + kc*16, B + (size_t)row*ldb + k0 + kc*4);
    }
}

// C[128,128] += A[128,K]*B[128,K]^T, K = nIter*16, 4-stage cp.async pipeline
static __device__ __forceinline__ void gemm_cp(uint32_t smb, float (&acc)[4][4][4],
    const float* __restrict__ A, size_t lda,
    const float* __restrict__ B, size_t ldb, int nIter, int aoff, int boff)
{
    const int tid = threadIdx.x;
    #pragma unroll
    for (int s = 0; s < 3; s++){
        if (s < nIter) cp_issue(smb + s*STG, A, lda, B, ldb, s*16, tid);
        CP_COMMIT();
    }
    for (int kt = 0; kt < nIter; kt++){
        CP_WAIT2();
        __syncthreads();
        if (kt + 3 < nIter) cp_issue(smb + ((kt+3)&3)*STG, A, lda, B, ldb, (kt+3)*16, tid);
        CP_COMMIT();
        compute16(smb + (kt&3)*STG, acc, aoff, boff);
    }
}

#define GEMM_PROLOGUE() \
    extern __shared__ char sm[]; \
    const uint32_t smb = smem_u32(sm); \
    const int tid = threadIdx.x; \
    const int w = tid >> 5, wm = w >> 2, wn = w & 3, l = tid & 31; \
    const int fg = l >> 2, ft = l & 3; \
    const int aoff = (wm*64 + (l&15))*PITCH + ((l>>4)<<4); \
    const int boff = (wn*32 + (l&7))*PITCH + (((l>>3)&1)<<4); \
    float acc[4][4][4]; \
    _Pragma("unroll") for (int mi = 0; mi < 4; mi++) \
    _Pragma("unroll") for (int ni = 0; ni < 4; ni++) \
    _Pragma("unroll") for (int j = 0; j < 4; j++) acc[mi][ni][j] = 0.f;

// ======================= pre-round inputs to tf32 bit patterns =======================
__global__ void k_round(const float4* __restrict__ src, float4* __restrict__ dst, int n4)
{
    for (int i = blockIdx.x*blockDim.x + threadIdx.x; i < n4; i += gridDim.x*blockDim.x){
        float4 v = src[i];
        dst[i] = make_float4(rnd(v.x), rnd(v.y), rnd(v.z), rnd(v.w));
    }
}

// ======================= QKV GEMM + fused bias/RoPE + V transpose =======================
__global__ __launch_bounds__(256, 2) void k_qkv(const float* __restrict__ bias,
                                                const float* __restrict__ cs,
                                                const float* __restrict__ sn)
{
    GEMM_PROLOGUE();
    const int n0 = blockIdx.x * 128, m0 = blockIdx.y * 128;
    gemm_cp(smb, acc, g_x + (size_t)m0*DDIM, DDIM, g_w + (size_t)n0*DDIM, DDIM, DDIM/16,
            aoff, boff);
    __syncthreads();

    float* smC = (float*)sm;
    #pragma unroll
    for (int ni = 0; ni < 4; ni++){
        const int c = 32*wn + 8*ni + 2*ft;
        const float b0 = bias[n0 + c], b1 = bias[n0 + c + 1];
        #pragma unroll
        for (int mi = 0; mi < 4; mi++){
            const int rr = 64*wm + 16*mi + fg;
            smC[rr*132 + c]     = acc[mi][ni][0] + b0;
            smC[rr*132 + c + 1] = acc[mi][ni][1] + b1;
            smC[(rr+8)*132 + c]     = acc[mi][ni][2] + b0;
            smC[(rr+8)*132 + c + 1] = acc[mi][ni][3] + b1;
        }
    }
    __syncthreads();

    const int s = n0 >> 11, h = (n0 & 2047) >> 7;
    const int bb = m0 >> 11, t0 = m0 & 2047;
    if (s < 2){
        const int r = tid & 127, half = tid >> 7;
        const int t = t0 + r;
        float* dst = (s ? g_k : g_q) + ((size_t)(bb*NH + h)*TT + t)*HD;
        const float* csr = cs + (size_t)t*HD;
        const float* snr = sn + (size_t)t*HD;
        #pragma unroll
        for (int jj = 0; jj < 8; jj++){
            const int c = half*32 + jj*4;
            float4 x1 = *(const float4*)(smC + r*132 + c);
            float4 x2 = *(const float4*)(smC + r*132 + c + 64);
            float4 c0 = *(const float4*)(csr + c);
            float4 s0 = *(const float4*)(snr + c);
            float4 c1 = *(const float4*)(csr + c + 64);
            float4 s1 = *(const float4*)(snr + c + 64);
            *(float4*)(dst + c) = make_float4(
                rnd(x1.x*c0.x - x2.x*s0.x), rnd(x1.y*c0.y - x2.y*s0.y),
                rnd(x1.z*c0.z - x2.z*s0.z), rnd(x1.w*c0.w - x2.w*s0.w));
            *(float4*)(dst + c + 64) = make_float4(
                rnd(x2.x*c1.x + x1.x*s1.x), rnd(x2.y*c1.y + x1.y*s1.y),
                rnd(x2.z*c1.z + x1.z*s1.z), rnd(x2.w*c1.w + x1.w*s1.w));
        }
    } else {
        float* dstb = g_vt + (size_t)(bb*NH + h)*HD*TT;
        #pragma unroll
        for (int i = 0; i < 16; i++){
            const int ii = tid + i*256;
            const int d = ii >> 5, tq = ii & 31;
            *(float4*)(dstb + (size_t)d*TT + t0 + tq*4) = make_float4(
                rnd(smC[(tq*4 + 0)*132 + d]), rnd(smC[(tq*4 + 1)*132 + d]),
                rnd(smC[(tq*4 + 2)*132 + d]), rnd(smC[(tq*4 + 3)*132 + d]));
        }
    }
}

// ======================= Scores: S = scale * Q K^T, lower tiles only =======================
__global__ __launch_bounds__(256, 2) void k_scores()
{
    if (blockIdx.x > blockIdx.y) return;
    GEMM_PROLOGUE();
    const int bh = blockIdx.z;
    const int m0 = blockIdx.y * 128, n0 = blockIdx.x * 128;
    gemm_cp(smb, acc,
            g_q + (size_t)bh*TT*HD + (size_t)m0*HD, HD,
            g_k + (size_t)bh*TT*HD + (size_t)n0*HD, HD, HD/16, aoff, boff);
    float* C = g_s + (size_t)bh*TT*TT;
    #pragma unroll
    for (int mi = 0; mi < 4; mi++){
        const int rl = m0 + 64*wm + 16*mi + fg;
        #pragma unroll
        for (int ni = 0; ni < 4; ni++){
            const int c = n0 + 32*wn + 8*ni + 2*ft;
            *(float2*)(C + (size_t)rl*TT + c)     = make_float2(acc[mi][ni][0]*SCALE, acc[mi][ni][1]*SCALE);
            *(float2*)(C + (size_t)(rl+8)*TT + c) = make_float2(acc[mi][ni][2]*SCALE, acc[mi][ni][3]*SCALE);
        }
    }
}

// ------------------ PV staging helper: softmax transform + tf32 round ------------------
static __device__ __forceinline__ void pv_stA(char* buf, int row, int kc, float4 v,
                                              int k0, float mm, float ii, int L)
{
    const int jb = k0 + kc*4;
    uint4 o;
    o.x = (jb + 0 < L) ? f2tf32(__expf(v.x - mm)*ii) : 0u;
    o.y = (jb + 1 < L) ? f2tf32(__expf(v.y - mm)*ii) : 0u;
    o.z = (jb + 2 < L) ? f2tf32(__expf(v.z - mm)*ii) : 0u;
    o.w = (jb + 3 < L) ? f2tf32(__expf(v.w - mm)*ii) : 0u;
    *(uint4*)(buf + row*PITCH + kc*16) = o;
}

// ======================= PV with fused softmax: O = softmax(S) * V =======================
__global__ __launch_bounds__(256, 2) void k_pv()
{
    __shared__ float sM[128], sInv[128];
    GEMM_PROLOGUE();
    const int mt = blockIdx.x, bh = blockIdx.y;
    const int m0 = mt * 128;
    const float* Sr = g_s + (size_t)bh*TT*TT + (size_t)m0*TT;
    const float* Vt = g_vt + (size_t)bh*HD*TT;
    const int nIter = (mt + 1) * 8;

    // phase 1: per-row online max/sum over causal length
    #pragma unroll 1
    for (int rr = 0; rr < 16; rr++){
        const int r = w*16 + rr;
        const int L = m0 + r + 1;
        const float* row = Sr + (size_t)r*TT;
        float mloc = -FLT_MAX, sloc = 0.f;
        for (int j0 = l*4; j0 < L; j0 += 128){
            float4 v4 = *(const float4*)(row + j0);
            const float vx[4] = {v4.x, v4.y, v4.z, v4.w};
            float m4 = -FLT_MAX;
            #pragma unroll
            for (int e = 0; e < 4; e++) if (j0 + e < L) m4 = fmaxf(m4, vx[e]);
            if (m4 > mloc){ sloc *= __expf(mloc - m4); mloc = m4; }
            #pragma unroll
            for (int e = 0; e < 4; e++) if (j0 + e < L) sloc += __expf(vx[e] - mloc);
        }
        #pragma unroll
        for (int o = 16; o; o >>= 1){
            const float mo = __shfl_xor_sync(0xffffffffu, mloc, o);
            const float so = __shfl_xor_sync(0xffffffffu, sloc, o);
            const float mn = fmaxf(mloc, mo);
            sloc = sloc*__expf(mloc - mn) + so*__expf(mo - mn);
            mloc = mn;
        }
        if (l == 0){ sM[r] = mloc; sInv[r] = 1.f / sloc; }
    }
    __syncthreads();

    // manual 2-stage mainloop (A: exp transform; B: pre-rounded V^T)
    {
        const int row0 = tid >> 2, kc = tid & 3;
        const int row1 = row0 + 64;
        const float mf0 = sM[row0], if0 = sInv[row0];
        const float mf1 = sM[row1], if1 = sInv[row1];
        const int L0 = m0 + row0 + 1, L1 = m0 + row1 + 1;
        const float* A0 = Sr + (size_t)row0*TT + kc*4;
        const float* A1 = Sr + (size_t)row1*TT + kc*4;
        const float* B0 = Vt + (size_t)row0*TT + kc*4;
        const float* B1 = Vt + (size_t)row1*TT + kc*4;
        float4 pa0 = *(const float4*)A0, pa1 = *(const float4*)A1;
        float4 pb0 = *(const float4*)B0, pb1 = *(const float4*)B1;

        pv_stA(sm, row0, kc, pa0, 0, mf0, if0, L0);
        pv_stA(sm, row1, kc, pa1, 0, mf1, if1, L1);
        *(float4*)(sm + ASZ + row0*PITCH + kc*16) = pb0;
        *(float4*)(sm + ASZ + row1*PITCH + kc*16) = pb1;
        if (nIter > 1){
            pa0 = *(const float4*)(A0 + 16); pa1 = *(const float4*)(A1 + 16);
            pb0 = *(const float4*)(B0 + 16); pb1 = *(const float4*)(B1 + 16);
        }
        __syncthreads();
        for (int kt = 0; kt < nIter; kt++){
            if (kt + 1 < nIter){
                char* nb = sm + ((kt+1)&1)*STG;
                pv_stA(nb, row0, kc, pa0, (kt+1)*16, mf0, if0, L0);
                pv_stA(nb, row1, kc, pa1, (kt+1)*16, mf1, if1, L1);
                *(float4*)(nb + ASZ + row0*PITCH + kc*16) = pb0;
                *(float4*)(nb + ASZ + row1*PITCH + kc*16) = pb1;
            }
            if (kt + 2 < nIter){
                const int ko = (kt + 2) * 16;
                pa0 = *(const float4*)(A0 + ko); pa1 = *(const float4*)(A1 + ko);
                pb0 = *(const float4*)(B0 + ko); pb1 = *(const float4*)(B1 + ko);
            }
            compute16(smb + (kt&1)*STG, acc, aoff, boff);
            __syncthreads();
        }
    }

    const int bb = bh >> 4, h = bh & 15;
    #pragma unroll
    for (int mi = 0; mi < 4; mi++){
        const int m = m0 + 64*wm + 16*mi + fg;
        float* d0 = g_attn + ((size_t)(bb*TT + m))*DDIM + h*HD;
        float* d1 = g_attn + ((size_t)(bb*TT + m + 8))*DDIM + h*HD;
        #pragma unroll
        for (int ni = 0; ni < 4; ni++){
            const int c = 32*wn + 8*ni + 2*ft;
            *(float2*)(d0 + c) = make_float2(rnd(acc[mi][ni][0]), rnd(acc[mi][ni][1]));
            *(float2*)(d1 + c) = make_float2(rnd(acc[mi][ni][2]), rnd(acc[mi][ni][3]));
        }
    }
}

// ======================= Output projection =======================
__global__ __launch_bounds__(256, 2) void k_out(const float* __restrict__ bias,
                                                float* __restrict__ Cout)
{
    GEMM_PROLOGUE();
    const int n0 = blockIdx.x * 128, m0 = blockIdx.y * 128;
    gemm_cp(smb, acc, g_attn + (size_t)m0*DDIM, DDIM, g_wo + (size_t)n0*DDIM, DDIM,
            DDIM/16, aoff, boff);
    #pragma unroll
    for (int ni = 0; ni < 4; ni++){
        const int c = n0 + 32*wn + 8*ni + 2*ft;
        const float b0 = bias[c], b1 = bias[c + 1];
        #pragma unroll
        for (int mi = 0; mi < 4; mi++){
            const int m = m0 + 64*wm + 16*mi + fg;
            *(float2*)(Cout + (size_t)m*DDIM + c)     = make_float2(acc[mi][ni][0] + b0, acc[mi][ni][1] + b1);
            *(float2*)(Cout + (size_t)(m+8)*DDIM + c) = make_float2(acc[mi][ni][2] + b0, acc[mi][ni][3] + b1);
        }
    }
}

// ======================= launch =======================
extern "C" void kernel_launch(void* const* d_in, const int* in_sizes, int n_in,
                              void* d_out, int out_size)
{
    (void)in_sizes; (void)n_in; (void)out_size;
    const float* x      = (const float*)d_in[0];
    const float* rc     = (const float*)d_in[1];
    const float* rs     = (const float*)d_in[2];
    const float* qkv_w  = (const float*)d_in[3];
    const float* qkv_b  = (const float*)d_in[4];
    const float* out_w  = (const float*)d_in[5];
    const float* out_b  = (const float*)d_in[6];
    float* out = (float*)d_out;

    cudaFuncSetAttribute(k_qkv,    cudaFuncAttributeMaxDynamicSharedMemorySize, SMEM_ALL);
    cudaFuncSetAttribute(k_scores, cudaFuncAttributeMaxDynamicSharedMemorySize, SMEM_ALL);
    cudaFuncSetAttribute(k_pv,     cudaFuncAttributeMaxDynamicSharedMemorySize, SMEM_ALL);
    cudaFuncSetAttribute(k_out,    cudaFuncAttributeMaxDynamicSharedMemorySize, SMEM_ALL);

    float *px, *pw, *pwo;
    cudaGetSymbolAddress((void**)&px,  g_x);
    cudaGetSymbolAddress((void**)&pw,  g_w);
    cudaGetSymbolAddress((void**)&pwo, g_wo);

    k_round<<<2048, 256>>>((const float4*)x,     (float4*)px,  MROWS*DDIM/4);
    k_round<<<3072, 256>>>((const float4*)qkv_w, (float4*)pw,  E3*DDIM/4);
    k_round<<<1024, 256>>>((const float4*)out_w, (float4*)pwo, DDIM*DDIM/4);

    k_qkv<<<dim3(E3/128, MROWS/128), 256, SMEM_ALL>>>(qkv_b, rc, rs);
    k_scores<<<dim3(TT/128, TT/128, BH), 256, SMEM_ALL>>>();
    k_pv<<<dim3(TT/128, BH), 256, SMEM_ALL>>>();
    k_out<<<dim3(DDIM/128, MROWS/128), 256, SMEM_ALL>>>(out_b, out);
}